// round 5
// baseline (speedup 1.0000x reference)
#include <cuda_runtime.h>
#include <cuda_bf16.h>
#include <cstdint>

// Problem constants (shapes are fixed by the dataset; N/E still derived at runtime)
#define Hdim 128
#define CH   4
#define ROWF (CH * Hdim)   // 512 floats per node

// ---------------------------------------------------------------------------
// Kernel 1: edge scatter-add.  agg[row[e], c, h] += x[col[e], c, h]
// One warp per edge: 512 floats = 128 float4 = 4 float4 per lane.
// Vector reductions (red.global.add.v4.f32, sm_90+) quarter the L2 atomic ops.
// NOTE: edge_index is int32 on device (JAX x64-disabled downgrades jnp.int64).
// ---------------------------------------------------------------------------
__global__ void __launch_bounds__(256) edge_scatter_kernel(
    const float* __restrict__ x,
    const int* __restrict__ edge_index,
    float* __restrict__ agg,
    int E)
{
    int gwarp = (blockIdx.x * blockDim.x + threadIdx.x) >> 5;
    int lane  = threadIdx.x & 31;
    if (gwarp >= E) return;

    int r = edge_index[gwarp];       // row (destination)
    int c = edge_index[E + gwarp];   // col (source)

    const float4* src = reinterpret_cast<const float4*>(x + (size_t)c * ROWF);
    float4* dst       = reinterpret_cast<float4*>(agg + (size_t)r * ROWF);

#pragma unroll
    for (int i = 0; i < 4; i++) {
        float4 v = src[lane + 32 * i];
        float4* p = dst + lane + 32 * i;
        asm volatile("red.global.add.v4.f32 [%0], {%1,%2,%3,%4};"
                     :: "l"(p), "f"(v.x), "f"(v.y), "f"(v.z), "f"(v.w)
                     : "memory");
    }
}

// ---------------------------------------------------------------------------
// Kernel 2: fused output GEMM.
// For channel c (blockIdx.y): rows m = node index within a 128-row tile.
//   out[n,c,:] = x[n,c,:] @ Wroot^T + agg[n,c,:] @ Wrel^T (+ bias if c==0)
// Treated as C(M x 128) = A(M x 256) @ B(256 x 128) with
//   A[m, k]    = k<128 ? x[n,c,k]     : agg[n,c,k-128]   (agg lives in `out`)
//   B[k, o]    = k<128 ? Wroot[o][k]  : Wrel[o][k-128]
// 128x128 tile per block, 256 threads, 8x8 register blocking, BK=16.
// agg is read from `out` and overwritten in the epilogue (row-tile x channel
// pairs are block-exclusive, so no cross-block hazard).
// ---------------------------------------------------------------------------
#define BK    16
#define TM    128
#define PITCH 132   // 132 floats = 528 B, divisible by 4 floats -> float4 rows

__global__ void __launch_bounds__(256) fused_out_kernel(
    const float* __restrict__ x,
    float* __restrict__ out,          // holds agg on entry, final output on exit
    const float* __restrict__ W_s_rel,
    const float* __restrict__ W_s_root,
    const float* __restrict__ b_s_root,
    const float* __restrict__ W_v_rel,
    const float* __restrict__ W_v_root,
    int N)
{
    __shared__ float As[BK][PITCH];   // A tile, transposed: As[k][m]
    __shared__ float Bs[BK][PITCH];   // B tile:             Bs[k][o]

    const int c  = blockIdx.y;
    const int n0 = blockIdx.x * TM;
    const float* Wroot = (c == 0) ? W_s_root : W_v_root;
    const float* Wrel  = (c == 0) ? W_s_rel  : W_v_rel;

    const int t  = threadIdx.x;
    const int tx = t & 15;    // output-col group (8 cols)
    const int ty = t >> 4;    // output-row group (8 rows)

    float acc[8][8];
#pragma unroll
    for (int i = 0; i < 8; i++)
#pragma unroll
        for (int j = 0; j < 8; j++) acc[i][j] = 0.0f;

    for (int kk = 0; kk < 2 * Hdim; kk += BK) {
        const bool  root = (kk < Hdim);
        const int   kb   = kk & (Hdim - 1);
        const float* Bsrc = root ? Wroot : Wrel;
        const float* Asrc = root ? x : out;

        // ---- stage B: 16(k) x 128(o) from W[o][kb..kb+15], coalesced float4
#pragma unroll
        for (int rep = 0; rep < 2; rep++) {
            int idx = t + rep * 256;        // 0..511 float4 slots
            int o   = idx >> 2;             // 0..127
            int kq  = idx & 3;              // 0..3
            float4 v = *reinterpret_cast<const float4*>(Bsrc + (size_t)o * Hdim + kb + kq * 4);
            Bs[kq * 4 + 0][o] = v.x;
            Bs[kq * 4 + 1][o] = v.y;
            Bs[kq * 4 + 2][o] = v.z;
            Bs[kq * 4 + 3][o] = v.w;
        }

        // ---- stage A (transposed): rows are (n0+m)*4 + c, cols kb..kb+15
#pragma unroll
        for (int rep = 0; rep < 2; rep++) {
            int idx = t + rep * 256;
            int m   = idx >> 2;             // 0..127
            int kq  = idx & 3;
            int n   = n0 + m;
            float4 v = make_float4(0.f, 0.f, 0.f, 0.f);
            if (n < N)
                v = *reinterpret_cast<const float4*>(
                        Asrc + ((size_t)n * CH + c) * Hdim + kb + kq * 4);
            As[kq * 4 + 0][m] = v.x;
            As[kq * 4 + 1][m] = v.y;
            As[kq * 4 + 2][m] = v.z;
            As[kq * 4 + 3][m] = v.w;
        }

        __syncthreads();

#pragma unroll
        for (int k = 0; k < BK; k++) {
            float a0[8], b0[8];
            *reinterpret_cast<float4*>(&a0[0]) = *reinterpret_cast<const float4*>(&As[k][ty * 8]);
            *reinterpret_cast<float4*>(&a0[4]) = *reinterpret_cast<const float4*>(&As[k][ty * 8 + 4]);
            *reinterpret_cast<float4*>(&b0[0]) = *reinterpret_cast<const float4*>(&Bs[k][tx * 8]);
            *reinterpret_cast<float4*>(&b0[4]) = *reinterpret_cast<const float4*>(&Bs[k][tx * 8 + 4]);
#pragma unroll
            for (int i = 0; i < 8; i++)
#pragma unroll
                for (int j = 0; j < 8; j++)
                    acc[i][j] = fmaf(a0[i], b0[j], acc[i][j]);
        }

        __syncthreads();
    }

    // ---- epilogue: add bias for channel 0, write out (overwrites agg rows)
    float bias[8];
#pragma unroll
    for (int j = 0; j < 8; j++)
        bias[j] = (c == 0) ? b_s_root[tx * 8 + j] : 0.0f;

#pragma unroll
    for (int i = 0; i < 8; i++) {
        int n = n0 + ty * 8 + i;
        if (n < N) {
            float* op = out + ((size_t)n * CH + c) * Hdim + tx * 8;
#pragma unroll
            for (int j = 0; j < 8; j += 4) {
                float4 v;
                v.x = acc[i][j + 0] + bias[j + 0];
                v.y = acc[i][j + 1] + bias[j + 1];
                v.z = acc[i][j + 2] + bias[j + 2];
                v.w = acc[i][j + 3] + bias[j + 3];
                *reinterpret_cast<float4*>(op + j) = v;
            }
        }
    }
}

// ---------------------------------------------------------------------------
extern "C" void kernel_launch(void* const* d_in, const int* in_sizes, int n_in,
                              void* d_out, int out_size)
{
    const float* x        = (const float*)d_in[0];
    const int*   ei       = (const int*)d_in[1];     // int32! (JAX x64 disabled)
    const float* W_s_rel  = (const float*)d_in[2];
    const float* W_s_root = (const float*)d_in[3];
    const float* b_s_root = (const float*)d_in[4];
    const float* W_v_rel  = (const float*)d_in[5];
    const float* W_v_root = (const float*)d_in[6];
    float*       out      = (float*)d_out;

    int N = in_sizes[0] / ROWF;
    int E = in_sizes[1] / 2;

    // 1) zero the agg/output buffer
    cudaMemsetAsync(out, 0, (size_t)out_size * sizeof(float));

    // 2) edge scatter-add (warp per edge)
    {
        int threads = 256;
        long long total = (long long)E * 32;
        int blocks = (int)((total + threads - 1) / threads);
        edge_scatter_kernel<<<blocks, threads>>>(x, ei, out, E);
    }

    // 3) fused output GEMM
    {
        dim3 grid((N + TM - 1) / TM, CH);
        fused_out_kernel<<<grid, 256>>>(x, out, W_s_rel, W_s_root, b_s_root,
                                        W_v_rel, W_v_root, N);
    }
}

// round 8
// speedup vs baseline: 1.8293x; 1.8293x over previous
#include <cuda_runtime.h>
#include <cuda_bf16.h>
#include <cstdint>

// Problem constants
#define Hdim 128
#define CH   4
#define ROWF (CH * Hdim)   // 512 floats per node

// ---------------------------------------------------------------------------
// Kernel 1: edge scatter-add (unchanged — passing).
// agg[row[e], c, h] += x[col[e], c, h];  warp per edge, red.global.add.v4.f32
// ---------------------------------------------------------------------------
__global__ void __launch_bounds__(256) edge_scatter_kernel(
    const float* __restrict__ x,
    const int* __restrict__ edge_index,
    float* __restrict__ agg,
    int E)
{
    int gwarp = (blockIdx.x * blockDim.x + threadIdx.x) >> 5;
    int lane  = threadIdx.x & 31;
    if (gwarp >= E) return;

    int r = edge_index[gwarp];       // row (destination)
    int c = edge_index[E + gwarp];   // col (source)

    const float4* src = reinterpret_cast<const float4*>(x + (size_t)c * ROWF);
    float4* dst       = reinterpret_cast<float4*>(agg + (size_t)r * ROWF);

#pragma unroll
    for (int i = 0; i < 4; i++) {
        float4 v = src[lane + 32 * i];
        float4* p = dst + lane + 32 * i;
        asm volatile("red.global.add.v4.f32 [%0], {%1,%2,%3,%4};"
                     :: "l"(p), "f"(v.x), "f"(v.y), "f"(v.z), "f"(v.w)
                     : "memory");
    }
}

// ---------------------------------------------------------------------------
// Kernel 2: tf32 mma.sync GEMM (sm_80-era PTX path — no arch-'a' gating).
// Per block: channel c = blockIdx.y, node tile n0 = blockIdx.x*128.
//   D[m][o] = sum_k A[m,k] * B[o,k],  M=128, N=128, K=256
//   A[m,k] = k<128 ? x[n,c,k] : agg[n,c,k-128]   (agg lives in `out`)
//   B[o,k] = k<128 ? Wroot[o][k] : Wrel[o][k]
// 8 warps, warp tile 32(m) x 64(n); m16n8k8 fragments, scalar LDS frag loads.
// SMEM tiles [k][col] with pitch 136 floats:
//   bank(addr) = (8k + col) mod 32  -> frag loads conflict-free
//   staging: lanes share k, col consecutive -> stores conflict-free
// ---------------------------------------------------------------------------
#define LDP 136          // smem row pitch in floats (136*4 B; 136 mod 32 == 8)
#define BKC 32           // K per chunk

__device__ __forceinline__ void mma_tf32(float d[4], const uint32_t a[4],
                                         const uint32_t b[2]) {
    asm volatile(
        "mma.sync.aligned.m16n8k8.row.col.f32.tf32.tf32.f32 "
        "{%0,%1,%2,%3}, {%4,%5,%6,%7}, {%8,%9}, {%0,%1,%2,%3};"
        : "+f"(d[0]), "+f"(d[1]), "+f"(d[2]), "+f"(d[3])
        : "r"(a[0]), "r"(a[1]), "r"(a[2]), "r"(a[3]), "r"(b[0]), "r"(b[1]));
}

__global__ void __launch_bounds__(256) fused_out_mma(
    const float* __restrict__ x,
    float* __restrict__ out,          // agg on entry, final output on exit
    const float* __restrict__ W_s_rel,
    const float* __restrict__ W_s_root,
    const float* __restrict__ b_s_root,
    const float* __restrict__ W_v_rel,
    const float* __restrict__ W_v_root,
    int N)
{
    __shared__ float As[BKC * LDP];   // [k][m], 17408 B
    __shared__ float Bs[BKC * LDP];   // [k][o], 17408 B

    const int c  = blockIdx.y;
    const int n0 = blockIdx.x * 128;
    const float* Wroot = (c == 0) ? W_s_root : W_v_root;
    const float* Wrel  = (c == 0) ? W_s_rel  : W_v_rel;

    const int t    = threadIdx.x;
    const int lane = t & 31;
    const int wid  = t >> 5;
    const int m0w  = (wid & 3) * 32;   // warp m origin
    const int n0w  = (wid >> 2) * 64;  // warp n origin
    const int grp  = lane >> 2;        // 0..7
    const int tig  = lane & 3;         // 0..3

    float acc[2][8][4];
#pragma unroll
    for (int im = 0; im < 2; im++)
#pragma unroll
        for (int jn = 0; jn < 8; jn++)
#pragma unroll
            for (int q = 0; q < 4; q++) acc[im][jn][q] = 0.0f;

    const uint32_t* Asu = reinterpret_cast<const uint32_t*>(As);
    const uint32_t* Bsu = reinterpret_cast<const uint32_t*>(Bs);

    for (int kc = 0; kc < 8; kc++) {
        const bool  root = (kc < 4);
        const int   kb   = (kc & 3) * BKC;     // k offset within the 128 half
        const float* Asrc = root ? x : out;
        const float* Bsrc = root ? Wroot : Wrel;

        __syncthreads();   // previous chunk's frag reads done before restage

        // ---- stage: slot = rep*256 + t; kq2 = slot>>7 (0..3), col = slot&127
        // Each slot loads 8 consecutive floats (32 B, sector-aligned) along k.
#pragma unroll
        for (int rep = 0; rep < 2; rep++) {
            int slot = rep * 256 + t;
            int kq2  = slot >> 7;               // 8-float group within chunk
            int m    = slot & 127;              // row (node-in-tile / weight row)
            int kofs = kb + kq2 * 8;

            // A: node rows (guard tail tile)
            int n = n0 + m;
            float4 a0 = make_float4(0.f, 0.f, 0.f, 0.f), a1 = a0;
            if (n < N) {
                const float* p = Asrc + ((size_t)n * CH + c) * Hdim + kofs;
                a0 = *reinterpret_cast<const float4*>(p);
                a1 = *reinterpret_cast<const float4*>(p + 4);
            }
            float* da = &As[(kq2 * 8) * LDP + m];
            da[0 * LDP] = a0.x; da[1 * LDP] = a0.y;
            da[2 * LDP] = a0.z; da[3 * LDP] = a0.w;
            da[4 * LDP] = a1.x; da[5 * LDP] = a1.y;
            da[6 * LDP] = a1.z; da[7 * LDP] = a1.w;

            // B: weight rows (always 128 rows, no guard)
            const float* q = Bsrc + (size_t)m * Hdim + kofs;
            float4 b0 = *reinterpret_cast<const float4*>(q);
            float4 b1 = *reinterpret_cast<const float4*>(q + 4);
            float* db = &Bs[(kq2 * 8) * LDP + m];
            db[0 * LDP] = b0.x; db[1 * LDP] = b0.y;
            db[2 * LDP] = b0.z; db[3 * LDP] = b0.w;
            db[4 * LDP] = b1.x; db[5 * LDP] = b1.y;
            db[6 * LDP] = b1.z; db[7 * LDP] = b1.w;
        }

        __syncthreads();

        // ---- compute: 4 k-steps of 8
#pragma unroll
        for (int ks = 0; ks < 4; ks++) {
            const int k0 = ks * 8;

            uint32_t af[2][4];
#pragma unroll
            for (int im = 0; im < 2; im++) {
                int mr = m0w + im * 16 + grp;
                af[im][0] = Asu[(k0 + tig) * LDP + mr];
                af[im][1] = Asu[(k0 + tig) * LDP + mr + 8];
                af[im][2] = Asu[(k0 + 4 + tig) * LDP + mr];
                af[im][3] = Asu[(k0 + 4 + tig) * LDP + mr + 8];
            }
#pragma unroll
            for (int jn = 0; jn < 8; jn++) {
                int nc = n0w + jn * 8 + grp;
                uint32_t bf[2];
                bf[0] = Bsu[(k0 + tig) * LDP + nc];
                bf[1] = Bsu[(k0 + 4 + tig) * LDP + nc];
                mma_tf32(acc[0][jn], af[0], bf);
                mma_tf32(acc[1][jn], af[1], bf);
            }
        }
    }

    // ---- epilogue: c0,c1 -> (row, col..col+1); c2,c3 -> (row+8, col..col+1)
#pragma unroll
    for (int im = 0; im < 2; im++) {
#pragma unroll
        for (int half = 0; half < 2; half++) {
            int row = m0w + im * 16 + grp + half * 8;
            int n   = n0 + row;
            if (n >= N) continue;
            float* op = out + ((size_t)n * CH + c) * Hdim;
#pragma unroll
            for (int jn = 0; jn < 8; jn++) {
                int col = n0w + jn * 8 + 2 * tig;
                float2 v;
                v.x = acc[im][jn][half * 2 + 0];
                v.y = acc[im][jn][half * 2 + 1];
                if (c == 0) {
                    v.x += b_s_root[col];
                    v.y += b_s_root[col + 1];
                }
                *reinterpret_cast<float2*>(op + col) = v;
            }
        }
    }
}

// ---------------------------------------------------------------------------
extern "C" void kernel_launch(void* const* d_in, const int* in_sizes, int n_in,
                              void* d_out, int out_size)
{
    const float* x        = (const float*)d_in[0];
    const int*   ei       = (const int*)d_in[1];     // int32 (JAX x64 disabled)
    const float* W_s_rel  = (const float*)d_in[2];
    const float* W_s_root = (const float*)d_in[3];
    const float* b_s_root = (const float*)d_in[4];
    const float* W_v_rel  = (const float*)d_in[5];
    const float* W_v_root = (const float*)d_in[6];
    float*       out      = (float*)d_out;

    int N = in_sizes[0] / ROWF;
    int E = in_sizes[1] / 2;

    // 1) zero the agg/output buffer
    cudaMemsetAsync(out, 0, (size_t)out_size * sizeof(float));

    // 2) edge scatter-add (warp per edge)
    {
        int threads = 256;
        long long total = (long long)E * 32;
        int blocks = (int)((total + threads - 1) / threads);
        edge_scatter_kernel<<<blocks, threads>>>(x, ei, out, E);
    }

    // 3) tf32 mma.sync fused output GEMM
    {
        dim3 grid((N + 127) / 128, CH);
        fused_out_mma<<<grid, 256>>>(x, out, W_s_rel, W_s_root, b_s_root,
                                     W_v_rel, W_v_root, N);
    }
}

// round 10
// speedup vs baseline: 1.9098x; 1.0440x over previous
#include <cuda_runtime.h>
#include <cuda_bf16.h>
#include <cstdint>

// Problem constants
#define Hdim 128
#define CH   4
#define ROWF (CH * Hdim)   // 512 floats per node

#define NMAX 65536
#define EMAX (1 << 20)

// Scratch (device globals — no allocation allowed)
__device__ __align__(16) int g_deg[NMAX];
__device__ __align__(16) int g_cur[NMAX];
__device__ __align__(16) int g_off[NMAX + 1];
__device__ __align__(16) int g_csr[EMAX];

// ---------------------------------------------------------------------------
// CSR build: zero degrees -> count -> scan -> fill
// ---------------------------------------------------------------------------
__global__ void zero_deg(int N) {
    int i = blockIdx.x * blockDim.x + threadIdx.x;
    if (i < N) g_deg[i] = 0;
}

__global__ void deg_count(const int* __restrict__ ei, int E) {
    int e = blockIdx.x * blockDim.x + threadIdx.x;
    if (e < E) atomicAdd(&g_deg[ei[e]], 1);
}

// Single-block scan, 1024 threads, 8 elements/thread per pass.
#define SCAN_VT 8
__global__ void __launch_bounds__(1024) scan_offsets(int N) {
    __shared__ int wsum[32];
    __shared__ int s_carry;
    int tid = threadIdx.x, lane = tid & 31, wid = tid >> 5;
    if (tid == 0) s_carry = 0;
    __syncthreads();

    for (int base = 0; base < N; base += 1024 * SCAN_VT) {
        int idx0 = base + tid * SCAN_VT;
        int v[SCAN_VT];
#pragma unroll
        for (int j = 0; j < SCAN_VT; j++) {
            int i = idx0 + j;
            v[j] = (i < N) ? g_deg[i] : 0;
        }
#pragma unroll
        for (int j = 1; j < SCAN_VT; j++) v[j] += v[j - 1];
        int tot  = v[SCAN_VT - 1];
        int incl = tot;
#pragma unroll
        for (int d = 1; d < 32; d <<= 1) {
            int t = __shfl_up_sync(0xFFFFFFFFu, incl, d);
            if (lane >= d) incl += t;
        }
        if (lane == 31) wsum[wid] = incl;
        __syncthreads();
        if (wid == 0) {
            int w = wsum[lane], wi = w;
#pragma unroll
            for (int d = 1; d < 32; d <<= 1) {
                int t = __shfl_up_sync(0xFFFFFFFFu, wi, d);
                if (lane >= d) wi += t;
            }
            wsum[lane] = wi - w;   // exclusive warp offset
        }
        __syncthreads();
        int texcl = s_carry + wsum[wid] + incl - tot;
#pragma unroll
        for (int j = 0; j < SCAN_VT; j++) {
            int i = idx0 + j;
            if (i < N) {
                int o = texcl + (j ? v[j - 1] : 0);
                g_off[i] = o;
                g_cur[i] = o;
            }
        }
        __syncthreads();
        if (tid == 1023) s_carry = texcl + tot;
        __syncthreads();
    }
    if (tid == 0) g_off[N] = s_carry;
}

__global__ void csr_fill(const int* __restrict__ ei, int E) {
    int e = blockIdx.x * blockDim.x + threadIdx.x;
    if (e >= E) return;
    int r   = ei[e];
    int col = ei[E + e];
    int pos = atomicAdd(&g_cur[r], 1);
    g_csr[pos] = col;
}

// ---------------------------------------------------------------------------
// Gather-accumulate: agg[row, ch*128 + 0..127] = sum over CSR edges of
// x[col, ...]. One warp per (row, 128-float chunk); one float4 per lane.
// Writes every row (zero for degree-0), so no memset needed.
// ---------------------------------------------------------------------------
__global__ void __launch_bounds__(256) csr_gather(
    const float* __restrict__ x, float* __restrict__ out, int N)
{
    int gw   = (blockIdx.x * blockDim.x + threadIdx.x) >> 5;
    int lane = threadIdx.x & 31;
    int row  = gw >> 2;
    int ch   = gw & 3;
    if (row >= N) return;

    int s = g_off[row];
    int e = g_off[row + 1];

    const float* xb = x + ch * 128 + lane * 4;
    float4 acc = make_float4(0.f, 0.f, 0.f, 0.f);

    int i = s;
    for (; i + 1 < e; i += 2) {
        int c0 = g_csr[i], c1 = g_csr[i + 1];
        float4 v0 = *reinterpret_cast<const float4*>(xb + (size_t)c0 * ROWF);
        float4 v1 = *reinterpret_cast<const float4*>(xb + (size_t)c1 * ROWF);
        acc.x += v0.x + v1.x;
        acc.y += v0.y + v1.y;
        acc.z += v0.z + v1.z;
        acc.w += v0.w + v1.w;
    }
    if (i < e) {
        int c0 = g_csr[i];
        float4 v0 = *reinterpret_cast<const float4*>(xb + (size_t)c0 * ROWF);
        acc.x += v0.x; acc.y += v0.y; acc.z += v0.z; acc.w += v0.w;
    }
    *reinterpret_cast<float4*>(out + (size_t)row * ROWF + ch * 128 + lane * 4) = acc;
}

// ---------------------------------------------------------------------------
// tf32 mma.sync GEMM with 3-MMA error compensation (rel_err ~1e-6).
//   D[m][o] = sum_k A[m,k]*B[o,k],  M=128, N=128, K=256, per (tile, channel)
//   a = a_big + a_small (exact fp32 split at tf32-rna boundary);
//   acc += big*big + small*big + big*small
// ---------------------------------------------------------------------------
#define LDP 136          // smem row pitch in floats (136 mod 32 == 8)
#define BKC 32           // K per chunk

__device__ __forceinline__ void mma_tf32(float d[4], const uint32_t a[4],
                                         const uint32_t b[2]) {
    asm volatile(
        "mma.sync.aligned.m16n8k8.row.col.f32.tf32.tf32.f32 "
        "{%0,%1,%2,%3}, {%4,%5,%6,%7}, {%8,%9}, {%0,%1,%2,%3};"
        : "+f"(d[0]), "+f"(d[1]), "+f"(d[2]), "+f"(d[3])
        : "r"(a[0]), "r"(a[1]), "r"(a[2]), "r"(a[3]), "r"(b[0]), "r"(b[1]));
}

__device__ __forceinline__ uint32_t f2tf32(float f) {
    uint32_t r;
    asm("cvt.rna.tf32.f32 %0, %1;" : "=r"(r) : "f"(f));
    return r;
}

__global__ void __launch_bounds__(256, 2) fused_out_mma(
    const float* __restrict__ x,
    float* __restrict__ out,          // agg on entry, final output on exit
    const float* __restrict__ W_s_rel,
    const float* __restrict__ W_s_root,
    const float* __restrict__ b_s_root,
    const float* __restrict__ W_v_rel,
    const float* __restrict__ W_v_root,
    int N)
{
    __shared__ float As[BKC * LDP];   // [k][m]
    __shared__ float Bs[BKC * LDP];   // [k][o]

    const int c  = blockIdx.y;
    const int n0 = blockIdx.x * 128;
    const float* Wroot = (c == 0) ? W_s_root : W_v_root;
    const float* Wrel  = (c == 0) ? W_s_rel  : W_v_rel;

    const int t    = threadIdx.x;
    const int lane = t & 31;
    const int wid  = t >> 5;
    const int m0w  = (wid & 3) * 32;   // warp m origin
    const int n0w  = (wid >> 2) * 64;  // warp n origin
    const int grp  = lane >> 2;        // 0..7
    const int tig  = lane & 3;         // 0..3

    float acc[2][8][4];
#pragma unroll
    for (int im = 0; im < 2; im++)
#pragma unroll
        for (int jn = 0; jn < 8; jn++)
#pragma unroll
            for (int q = 0; q < 4; q++) acc[im][jn][q] = 0.0f;

    for (int kc = 0; kc < 8; kc++) {
        const bool  root = (kc < 4);
        const int   kb   = (kc & 3) * BKC;
        const float* Asrc = root ? x : out;
        const float* Bsrc = root ? Wroot : Wrel;

        __syncthreads();   // previous chunk's frag reads done before restage

#pragma unroll
        for (int rep = 0; rep < 2; rep++) {
            int slot = rep * 256 + t;
            int kq2  = slot >> 7;
            int m    = slot & 127;
            int kofs = kb + kq2 * 8;

            int n = n0 + m;
            float4 a0 = make_float4(0.f, 0.f, 0.f, 0.f), a1 = a0;
            if (n < N) {
                const float* p = Asrc + ((size_t)n * CH + c) * Hdim + kofs;
                a0 = *reinterpret_cast<const float4*>(p);
                a1 = *reinterpret_cast<const float4*>(p + 4);
            }
            float* da = &As[(kq2 * 8) * LDP + m];
            da[0 * LDP] = a0.x; da[1 * LDP] = a0.y;
            da[2 * LDP] = a0.z; da[3 * LDP] = a0.w;
            da[4 * LDP] = a1.x; da[5 * LDP] = a1.y;
            da[6 * LDP] = a1.z; da[7 * LDP] = a1.w;

            const float* q = Bsrc + (size_t)m * Hdim + kofs;
            float4 b0 = *reinterpret_cast<const float4*>(q);
            float4 b1 = *reinterpret_cast<const float4*>(q + 4);
            float* db = &Bs[(kq2 * 8) * LDP + m];
            db[0 * LDP] = b0.x; db[1 * LDP] = b0.y;
            db[2 * LDP] = b0.z; db[3 * LDP] = b0.w;
            db[4 * LDP] = b1.x; db[5 * LDP] = b1.y;
            db[6 * LDP] = b1.z; db[7 * LDP] = b1.w;
        }

        __syncthreads();

#pragma unroll
        for (int ks = 0; ks < 4; ks++) {
            const int k0 = ks * 8;

            uint32_t aB[2][4], aS[2][4];
#pragma unroll
            for (int im = 0; im < 2; im++) {
                int mr = m0w + im * 16 + grp;
                float af[4];
                af[0] = As[(k0 + tig) * LDP + mr];
                af[1] = As[(k0 + tig) * LDP + mr + 8];
                af[2] = As[(k0 + 4 + tig) * LDP + mr];
                af[3] = As[(k0 + 4 + tig) * LDP + mr + 8];
#pragma unroll
                for (int q = 0; q < 4; q++) {
                    aB[im][q] = f2tf32(af[q]);
                    aS[im][q] = __float_as_uint(af[q] - __uint_as_float(aB[im][q]));
                }
            }
#pragma unroll
            for (int jn = 0; jn < 8; jn++) {
                int nc = n0w + jn * 8 + grp;
                float bf0 = Bs[(k0 + tig) * LDP + nc];
                float bf1 = Bs[(k0 + 4 + tig) * LDP + nc];
                uint32_t bB[2], bS[2];
                bB[0] = f2tf32(bf0);
                bB[1] = f2tf32(bf1);
                bS[0] = __float_as_uint(bf0 - __uint_as_float(bB[0]));
                bS[1] = __float_as_uint(bf1 - __uint_as_float(bB[1]));

                mma_tf32(acc[0][jn], aB[0], bB);
                mma_tf32(acc[0][jn], aS[0], bB);
                mma_tf32(acc[0][jn], aB[0], bS);
                mma_tf32(acc[1][jn], aB[1], bB);
                mma_tf32(acc[1][jn], aS[1], bB);
                mma_tf32(acc[1][jn], aB[1], bS);
            }
        }
    }

    // ---- epilogue
#pragma unroll
    for (int im = 0; im < 2; im++) {
#pragma unroll
        for (int half = 0; half < 2; half++) {
            int row = m0w + im * 16 + grp + half * 8;
            int n   = n0 + row;
            if (n >= N) continue;
            float* op = out + ((size_t)n * CH + c) * Hdim;
#pragma unroll
            for (int jn = 0; jn < 8; jn++) {
                int col = n0w + jn * 8 + 2 * tig;
                float2 v;
                v.x = acc[im][jn][half * 2 + 0];
                v.y = acc[im][jn][half * 2 + 1];
                if (c == 0) {
                    v.x += b_s_root[col];
                    v.y += b_s_root[col + 1];
                }
                *reinterpret_cast<float2*>(op + col) = v;
            }
        }
    }
}

// ---------------------------------------------------------------------------
extern "C" void kernel_launch(void* const* d_in, const int* in_sizes, int n_in,
                              void* d_out, int out_size)
{
    const float* x        = (const float*)d_in[0];
    const int*   ei       = (const int*)d_in[1];     // int32 (JAX x64 disabled)
    const float* W_s_rel  = (const float*)d_in[2];
    const float* W_s_root = (const float*)d_in[3];
    const float* b_s_root = (const float*)d_in[4];
    const float* W_v_rel  = (const float*)d_in[5];
    const float* W_v_root = (const float*)d_in[6];
    float*       out      = (float*)d_out;

    int N = in_sizes[0] / ROWF;
    int E = in_sizes[1] / 2;

    // 1) CSR build
    zero_deg<<<(N + 255) / 256, 256>>>(N);
    deg_count<<<(E + 255) / 256, 256>>>(ei, E);
    scan_offsets<<<1, 1024>>>(N);
    csr_fill<<<(E + 255) / 256, 256>>>(ei, E);

    // 2) gather-accumulate (writes full agg, incl. zeros -> no memset)
    {
        long long warps = (long long)N * 4;
        int blocks = (int)((warps + 7) / 8);
        csr_gather<<<blocks, 256>>>(x, out, N);
    }

    // 3) compensated tf32 mma.sync fused output GEMM
    {
        dim3 grid((N + 127) / 128, CH);
        fused_out_mma<<<grid, 256>>>(x, out, W_s_rel, W_s_root, b_s_root,
                                     W_v_rel, W_v_root, N);
    }
}

// round 15
// speedup vs baseline: 2.2697x; 1.1884x over previous
#include <cuda_runtime.h>
#include <cuda_bf16.h>
#include <cstdint>

// Problem constants
#define Hdim 128
#define CH   4
#define ROWF (CH * Hdim)   // 512 floats per node

#define NMAX 65536
#define EMAX (1 << 20)

// Scratch (device globals — no allocation allowed)
__device__ __align__(16) int g_deg[NMAX];
__device__ __align__(16) int g_cur[NMAX];
__device__ __align__(16) int g_off[NMAX + 1];
__device__ __align__(16) int g_csr[EMAX];

// ---------------------------------------------------------------------------
// CSR build: zero degrees -> count -> scan -> fill
// ---------------------------------------------------------------------------
__global__ void zero_deg(int N) {
    int i = blockIdx.x * blockDim.x + threadIdx.x;
    if (i < N) g_deg[i] = 0;
}

__global__ void deg_count(const int* __restrict__ ei, int E) {
    int e = blockIdx.x * blockDim.x + threadIdx.x;
    if (e < E) atomicAdd(&g_deg[ei[e]], 1);
}

#define SCAN_VT 8
__global__ void __launch_bounds__(1024) scan_offsets(int N) {
    __shared__ int wsum[32];
    __shared__ int s_carry;
    int tid = threadIdx.x, lane = tid & 31, wid = tid >> 5;
    if (tid == 0) s_carry = 0;
    __syncthreads();

    for (int base = 0; base < N; base += 1024 * SCAN_VT) {
        int idx0 = base + tid * SCAN_VT;
        int v[SCAN_VT];
#pragma unroll
        for (int j = 0; j < SCAN_VT; j++) {
            int i = idx0 + j;
            v[j] = (i < N) ? g_deg[i] : 0;
        }
#pragma unroll
        for (int j = 1; j < SCAN_VT; j++) v[j] += v[j - 1];
        int tot  = v[SCAN_VT - 1];
        int incl = tot;
#pragma unroll
        for (int d = 1; d < 32; d <<= 1) {
            int t = __shfl_up_sync(0xFFFFFFFFu, incl, d);
            if (lane >= d) incl += t;
        }
        if (lane == 31) wsum[wid] = incl;
        __syncthreads();
        if (wid == 0) {
            int w = wsum[lane], wi = w;
#pragma unroll
            for (int d = 1; d < 32; d <<= 1) {
                int t = __shfl_up_sync(0xFFFFFFFFu, wi, d);
                if (lane >= d) wi += t;
            }
            wsum[lane] = wi - w;
        }
        __syncthreads();
        int texcl = s_carry + wsum[wid] + incl - tot;
#pragma unroll
        for (int j = 0; j < SCAN_VT; j++) {
            int i = idx0 + j;
            if (i < N) {
                int o = texcl + (j ? v[j - 1] : 0);
                g_off[i] = o;
                g_cur[i] = o;
            }
        }
        __syncthreads();
        if (tid == 1023) s_carry = texcl + tot;
        __syncthreads();
    }
    if (tid == 0) g_off[N] = s_carry;
}

__global__ void csr_fill(const int* __restrict__ ei, int E) {
    int e = blockIdx.x * blockDim.x + threadIdx.x;
    if (e >= E) return;
    int r   = ei[e];
    int col = ei[E + e];
    int pos = atomicAdd(&g_cur[r], 1);
    g_csr[pos] = col;
}

// ---------------------------------------------------------------------------
// Gather-accumulate (MLP=4): agg[row, ch] = sum x[col, ch]; warp per (row,ch).
// ---------------------------------------------------------------------------
__global__ void __launch_bounds__(256) csr_gather(
    const float* __restrict__ x, float* __restrict__ out, int N)
{
    int gw   = (blockIdx.x * blockDim.x + threadIdx.x) >> 5;
    int lane = threadIdx.x & 31;
    int row  = gw >> 2;
    int ch   = gw & 3;
    if (row >= N) return;

    int s = g_off[row];
    int e = g_off[row + 1];

    const float* xb = x + ch * 128 + lane * 4;
    float4 acc0 = make_float4(0.f, 0.f, 0.f, 0.f);
    float4 acc1 = make_float4(0.f, 0.f, 0.f, 0.f);

    int i = s;
    for (; i + 3 < e; i += 4) {
        int c0 = g_csr[i], c1 = g_csr[i + 1], c2 = g_csr[i + 2], c3 = g_csr[i + 3];
        float4 v0 = *reinterpret_cast<const float4*>(xb + (size_t)c0 * ROWF);
        float4 v1 = *reinterpret_cast<const float4*>(xb + (size_t)c1 * ROWF);
        float4 v2 = *reinterpret_cast<const float4*>(xb + (size_t)c2 * ROWF);
        float4 v3 = *reinterpret_cast<const float4*>(xb + (size_t)c3 * ROWF);
        acc0.x += v0.x + v1.x;  acc0.y += v0.y + v1.y;
        acc0.z += v0.z + v1.z;  acc0.w += v0.w + v1.w;
        acc1.x += v2.x + v3.x;  acc1.y += v2.y + v3.y;
        acc1.z += v2.z + v3.z;  acc1.w += v2.w + v3.w;
    }
    for (; i < e; i++) {
        int c0 = g_csr[i];
        float4 v0 = *reinterpret_cast<const float4*>(xb + (size_t)c0 * ROWF);
        acc0.x += v0.x; acc0.y += v0.y; acc0.z += v0.z; acc0.w += v0.w;
    }
    acc0.x += acc1.x; acc0.y += acc1.y; acc0.z += acc1.z; acc0.w += acc1.w;
    *reinterpret_cast<float4*>(out + (size_t)row * ROWF + ch * 128 + lane * 4) = acc0;
}

// ---------------------------------------------------------------------------
// tf32 mma.sync GEMM, cp.async double-buffered, 3-MMA compensation.
//   D[m][o] = sum_k A[m,k]*B[o,k],  M=128, N=128, K=256, per (tile, channel)
// SMEM layout [m][k] with pitch 36 floats (144 B rows, 16B-aligned for
// cp.async; frag-load bank = 4*grp + tig -> conflict-free).
// Two buffers: stage chunk kc+1 via cp.async while MMAs run on chunk kc.
// ---------------------------------------------------------------------------
#define KP   36                         // smem row pitch (floats)
#define TSZ  (128 * KP)                 // one tile: 4608 floats = 18432 B
#define SMEM_BYTES (4 * TSZ * 4)        // A0,B0,A1,B1 = 73728 B

__device__ __forceinline__ void mma_tf32(float d[4], const uint32_t a[4],
                                         const uint32_t b[2]) {
    asm volatile(
        "mma.sync.aligned.m16n8k8.row.col.f32.tf32.tf32.f32 "
        "{%0,%1,%2,%3}, {%4,%5,%6,%7}, {%8,%9}, {%0,%1,%2,%3};"
        : "+f"(d[0]), "+f"(d[1]), "+f"(d[2]), "+f"(d[3])
        : "r"(a[0]), "r"(a[1]), "r"(a[2]), "r"(a[3]), "r"(b[0]), "r"(b[1]));
}

__device__ __forceinline__ uint32_t f2tf32(float f) {
    uint32_t r;
    asm("cvt.rna.tf32.f32 %0, %1;" : "=r"(r) : "f"(f));
    return r;
}

__global__ void __launch_bounds__(256, 2) fused_out_mma(
    const float* __restrict__ x,
    float* __restrict__ out,          // agg on entry, final output on exit
    const float* __restrict__ W_s_rel,
    const float* __restrict__ W_s_root,
    const float* __restrict__ b_s_root,
    const float* __restrict__ W_v_rel,
    const float* __restrict__ W_v_root,
    int N)
{
    extern __shared__ float smem[];

    const int c  = blockIdx.y;
    const int n0 = blockIdx.x * 128;
    const float* Wroot = (c == 0) ? W_s_root : W_v_root;
    const float* Wrel  = (c == 0) ? W_s_rel  : W_v_rel;

    const int t    = threadIdx.x;
    const int lane = t & 31;
    const int wid  = t >> 5;
    const int m0w  = (wid & 3) * 32;   // warp m origin
    const int n0w  = (wid >> 2) * 64;  // warp n origin
    const int grp  = lane >> 2;        // 0..7
    const int tig  = lane & 3;         // 0..3

    const uint32_t smem_b = (uint32_t)__cvta_generic_to_shared(smem);

    float acc[2][8][4];
#pragma unroll
    for (int im = 0; im < 2; im++)
#pragma unroll
        for (int jn = 0; jn < 8; jn++)
#pragma unroll
            for (int q = 0; q < 4; q++) acc[im][jn][q] = 0.0f;

    // ---- stage chunk kc into buffer (kc&1) via cp.async, then commit
    auto stage = [&](int kc) {
        const bool  root = (kc < 4);
        const int   kb   = (kc & 3) * 32;
        const float* Asrc = root ? x : out;
        const float* Bsrc = root ? Wroot : Wrel;
        const uint32_t bufA = smem_b + (uint32_t)((kc & 1) * 2 * TSZ) * 4;
        const uint32_t bufB = bufA + (uint32_t)TSZ * 4;

#pragma unroll
        for (int rep = 0; rep < 4; rep++) {
            int slot = t + rep * 256;          // 0..1023
            int m = slot >> 3;                 // row 0..127
            int q = slot & 7;                  // 16B chunk within 32-float row

            // A (guard tail tile via src-size 0 => zero-fill)
            int n = n0 + m;
            const float* gA = (n < N)
                ? Asrc + ((size_t)n * CH + c) * Hdim + kb + q * 4 : Asrc;
            int szA = (n < N) ? 16 : 0;
            uint32_t dA = bufA + (uint32_t)(m * KP + q * 4) * 4;
            asm volatile("cp.async.cg.shared.global [%0], [%1], 16, %2;"
                         :: "r"(dA), "l"(gA), "r"(szA));

            // B (always full)
            const float* gB = Bsrc + (size_t)m * Hdim + kb + q * 4;
            uint32_t dB = bufB + (uint32_t)(m * KP + q * 4) * 4;
            asm volatile("cp.async.cg.shared.global [%0], [%1], 16;"
                         :: "r"(dB), "l"(gB));
        }
        asm volatile("cp.async.commit_group;");
    };

    stage(0);

    for (int kc = 0; kc < 8; kc++) {
        if (kc < 7) {
            stage(kc + 1);
            asm volatile("cp.async.wait_group %0;" :: "n"(1));
        } else {
            asm volatile("cp.async.wait_group %0;" :: "n"(0));
        }
        __syncthreads();

        const float* As = smem + (kc & 1) * 2 * TSZ;
        const float* Bs = As + TSZ;

#pragma unroll
        for (int ks = 0; ks < 4; ks++) {
            const int k0 = ks * 8;

            uint32_t aB[2][4], aS[2][4];
#pragma unroll
            for (int im = 0; im < 2; im++) {
                int mr = m0w + im * 16 + grp;
                float af[4];
                af[0] = As[mr * KP + k0 + tig];
                af[1] = As[(mr + 8) * KP + k0 + tig];
                af[2] = As[mr * KP + k0 + 4 + tig];
                af[3] = As[(mr + 8) * KP + k0 + 4 + tig];
#pragma unroll
                for (int q = 0; q < 4; q++) {
                    aB[im][q] = f2tf32(af[q]);
                    aS[im][q] = __float_as_uint(af[q] - __uint_as_float(aB[im][q]));
                }
            }
#pragma unroll
            for (int jn = 0; jn < 8; jn++) {
                int nc = n0w + jn * 8 + grp;
                float bf0 = Bs[nc * KP + k0 + tig];
                float bf1 = Bs[nc * KP + k0 + 4 + tig];
                uint32_t bB[2], bS[2];
                bB[0] = f2tf32(bf0);
                bB[1] = f2tf32(bf1);
                bS[0] = __float_as_uint(bf0 - __uint_as_float(bB[0]));
                bS[1] = __float_as_uint(bf1 - __uint_as_float(bB[1]));

                mma_tf32(acc[0][jn], aB[0], bB);
                mma_tf32(acc[0][jn], aS[0], bB);
                mma_tf32(acc[0][jn], aB[0], bS);
                mma_tf32(acc[1][jn], aB[1], bB);
                mma_tf32(acc[1][jn], aS[1], bB);
                mma_tf32(acc[1][jn], aB[1], bS);
            }
        }

        __syncthreads();
    }

    // ---- epilogue
#pragma unroll
    for (int im = 0; im < 2; im++) {
#pragma unroll
        for (int half = 0; half < 2; half++) {
            int row = m0w + im * 16 + grp + half * 8;
            int n   = n0 + row;
            if (n >= N) continue;
            float* op = out + ((size_t)n * CH + c) * Hdim;
#pragma unroll
            for (int jn = 0; jn < 8; jn++) {
                int col = n0w + jn * 8 + 2 * tig;
                float2 v;
                v.x = acc[im][jn][half * 2 + 0];
                v.y = acc[im][jn][half * 2 + 1];
                if (c == 0) {
                    v.x += b_s_root[col];
                    v.y += b_s_root[col + 1];
                }
                *reinterpret_cast<float2*>(op + col) = v;
            }
        }
    }
}

// ---------------------------------------------------------------------------
extern "C" void kernel_launch(void* const* d_in, const int* in_sizes, int n_in,
                              void* d_out, int out_size)
{
    const float* x        = (const float*)d_in[0];
    const int*   ei       = (const int*)d_in[1];     // int32 (JAX x64 disabled)
    const float* W_s_rel  = (const float*)d_in[2];
    const float* W_s_root = (const float*)d_in[3];
    const float* b_s_root = (const float*)d_in[4];
    const float* W_v_rel  = (const float*)d_in[5];
    const float* W_v_root = (const float*)d_in[6];
    float*       out      = (float*)d_out;

    int N = in_sizes[0] / ROWF;
    int E = in_sizes[1] / 2;

    // 1) CSR build
    zero_deg<<<(N + 255) / 256, 256>>>(N);
    deg_count<<<(E + 255) / 256, 256>>>(ei, E);
    scan_offsets<<<1, 1024>>>(N);
    csr_fill<<<(E + 255) / 256, 256>>>(ei, E);

    // 2) gather-accumulate (writes full agg, incl. zeros -> no memset)
    {
        long long warps = (long long)N * 4;
        int blocks = (int)((warps + 7) / 8);
        csr_gather<<<blocks, 256>>>(x, out, N);
    }

    // 3) compensated tf32 mma.sync GEMM, cp.async double-buffered
    {
        // No static guard (harness rule): idempotent, host-side, not captured.
        cudaFuncSetAttribute(fused_out_mma,
                             cudaFuncAttributeMaxDynamicSharedMemorySize,
                             SMEM_BYTES);
        dim3 grid((N + 127) / 128, CH);
        fused_out_mma<<<grid, 256, SMEM_BYTES>>>(x, out, W_s_rel, W_s_root,
                                                 b_s_root, W_v_rel, W_v_root, N);
    }
}